// round 2
// baseline (speedup 1.0000x reference)
#include <cuda_runtime.h>
#include <cuda_bf16.h>
#include <math.h>

// Problem constants (shapes fixed by the dataset)
#define MAXN 100000
#define MAXE 1000000
#define F 64
#define NLAYER 4
#define ALPHA 0.1f

// ---------------- device scratch (no cudaMalloc allowed) ----------------
__device__ int   g_is64;
__device__ int   g_cnt[MAXN];
__device__ int   g_ptr[MAXN + 1];
__device__ int   g_cur[MAXN];
__device__ int   g_rowv[MAXE];
__device__ int   g_colv[MAXE];
__device__ int   g_srcv[MAXE];
__device__ int   g_bsum[256];
__device__ float g_dis[MAXN];
__device__ float g_bufA[MAXN * F];
__device__ float g_bufB[MAXN * F];
__device__ float g_bufP[MAXN * F];
__device__ float g_t16[MAXN * 16];
__device__ float g_p16[MAXN * 16];
__device__ float g_y[MAXN];

// ---------------- dtype detection (int64 vs int32 edge_index) ----------------
__global__ void k_detect(const int* ei32) {
    if (threadIdx.x == 0 && blockIdx.x == 0) {
        int odd_or = 0;
        for (int i = 1; i < 256; i += 2) odd_or |= ei32[i];
        g_is64 = (odd_or == 0) ? 1 : 0;
    }
}

__global__ void k_zero_cnt(int n) {
    int i = blockIdx.x * blockDim.x + threadIdx.x;
    if (i < n) g_cnt[i] = 0;
}

// convert edges to int32 + in-degree histogram on col
__global__ void k_convert_count(const void* ei, int E) {
    int e = blockIdx.x * blockDim.x + threadIdx.x;
    if (e >= E) return;
    int r, c;
    if (g_is64) {
        const long long* p = (const long long*)ei;
        r = (int)p[e];
        c = (int)p[e + E];
    } else {
        const int* p = (const int*)ei;
        r = p[e];
        c = p[e + E];
    }
    g_rowv[e] = r;
    g_colv[e] = c;
    atomicAdd(&g_cnt[c], 1);
}

__global__ void k_dis(int n) {
    int i = blockIdx.x * blockDim.x + threadIdx.x;
    if (i < n) g_dis[i] = rsqrtf((float)g_cnt[i] + 1.0f);  // +1 self loop
}

// ---------------- exclusive scan (3 kernels) ----------------
__global__ void k_scan1(int n) {
    __shared__ int s[1024];
    int i = blockIdx.x * 1024 + threadIdx.x;
    int v = (i < n) ? g_cnt[i] : 0;
    s[threadIdx.x] = v;
    __syncthreads();
    for (int off = 1; off < 1024; off <<= 1) {
        int t = (threadIdx.x >= off) ? s[threadIdx.x - off] : 0;
        __syncthreads();
        s[threadIdx.x] += t;
        __syncthreads();
    }
    if (i < n) g_ptr[i] = s[threadIdx.x] - v;  // exclusive
    if (threadIdx.x == 1023) g_bsum[blockIdx.x] = s[1023];
}

__global__ void k_scan2(int nblocks) {
    if (threadIdx.x == 0 && blockIdx.x == 0) {
        int run = 0;
        for (int b = 0; b < nblocks; b++) {
            int t = g_bsum[b];
            g_bsum[b] = run;
            run += t;
        }
    }
}

__global__ void k_scan3(int n, int E) {
    int i = blockIdx.x * blockDim.x + threadIdx.x;
    if (i < n) {
        int p = g_ptr[i] + g_bsum[i >> 10];
        g_ptr[i] = p;
        g_cur[i] = p;
    }
    if (i == 0) g_ptr[n] = E;
}

__global__ void k_scatter(int E) {
    int e = blockIdx.x * blockDim.x + threadIdx.x;
    if (e >= E) return;
    int c = g_colv[e];
    int pos = atomicAdd(&g_cur[c], 1);
    g_srcv[pos] = g_rowv[e];
}

// ---------------- propagates (CSR gather, self-loop folded in) ----------------
// 64 threads per node (one per feature)
__global__ void k_prop64(const float* __restrict__ hin, float* __restrict__ hout, int n) {
    int node = blockIdx.x * 4 + (threadIdx.x >> 6);
    int f = threadIdx.x & 63;
    if (node >= n) return;
    int beg = g_ptr[node], end = g_ptr[node + 1];
    float s = 0.f;
    for (int e = beg; e < end; e++) {
        int src = g_srcv[e];
        s += g_dis[src] * hin[src * F + f];
    }
    float d = g_dis[node];
    hout[node * F + f] = d * s + d * d * hin[node * F + f];
}

// 16 threads per node; adds bias b1 (applied after propagate in reference)
__global__ void k_prop16(const float* __restrict__ hin, float* __restrict__ hout,
                         const float* __restrict__ b1, int n) {
    int node = blockIdx.x * 16 + (threadIdx.x >> 4);
    int f = threadIdx.x & 15;
    if (node >= n) return;
    int beg = g_ptr[node], end = g_ptr[node + 1];
    float s = 0.f;
    for (int e = beg; e < end; e++) {
        int src = g_srcv[e];
        s += g_dis[src] * hin[src * 16 + f];
    }
    float d = g_dis[node];
    hout[node * 16 + f] = d * s + d * d * hin[node * 16 + f] + b1[f];
}

// scalar propagate + bias + sigmoid -> final output
__global__ void k_prop1_sig(const float* __restrict__ y, const float* __restrict__ b2,
                            float* __restrict__ out, int n) {
    int node = blockIdx.x * blockDim.x + threadIdx.x;
    if (node >= n) return;
    int beg = g_ptr[node], end = g_ptr[node + 1];
    float s = 0.f;
    for (int e = beg; e < end; e++) {
        int src = g_srcv[e];
        s += g_dis[src] * y[src];
    }
    float d = g_dis[node];
    float v = d * s + d * d * y[node] + b2[0];
    out[node] = 1.0f / (1.0f + expf(-v));
}

// ---------------- fused mix + GEMM(64x64) + relu ----------------
// hout = relu(((1-a)*P + a*X0) @ W), W row-major [k][j]
#define SA 68
__global__ void k_gemm_mix_relu(const float* __restrict__ P, const float* __restrict__ X0,
                                const float* __restrict__ W, float* __restrict__ Out, int n) {
    __shared__ float Ws[64 * SA];
    __shared__ float As[64 * SA];
    int tid = threadIdx.x;  // 256 threads
    for (int i = tid; i < 4096; i += 256)
        Ws[(i >> 6) * SA + (i & 63)] = W[i];
    int r0 = blockIdx.x * 64;
    for (int i = tid; i < 4096; i += 256) {
        int rr = i >> 6, j = i & 63;
        int r = r0 + rr;
        float v = 0.f;
        if (r < n) v = (1.0f - ALPHA) * P[r * F + j] + ALPHA * X0[r * F + j];
        As[rr * SA + j] = v;
    }
    __syncthreads();
    int tx = tid & 15, ty = tid >> 4;
    float acc[4][4] = {};
#pragma unroll 8
    for (int k = 0; k < 64; k++) {
        float4 w4 = *(const float4*)&Ws[k * SA + tx * 4];
        float a0 = As[(ty * 4 + 0) * SA + k];
        float a1 = As[(ty * 4 + 1) * SA + k];
        float a2 = As[(ty * 4 + 2) * SA + k];
        float a3 = As[(ty * 4 + 3) * SA + k];
        acc[0][0] += a0 * w4.x; acc[0][1] += a0 * w4.y; acc[0][2] += a0 * w4.z; acc[0][3] += a0 * w4.w;
        acc[1][0] += a1 * w4.x; acc[1][1] += a1 * w4.y; acc[1][2] += a1 * w4.z; acc[1][3] += a1 * w4.w;
        acc[2][0] += a2 * w4.x; acc[2][1] += a2 * w4.y; acc[2][2] += a2 * w4.z; acc[2][3] += a2 * w4.w;
        acc[3][0] += a3 * w4.x; acc[3][1] += a3 * w4.y; acc[3][2] += a3 * w4.z; acc[3][3] += a3 * w4.w;
    }
#pragma unroll
    for (int i = 0; i < 4; i++) {
        int r = r0 + ty * 4 + i;
        if (r < n) {
            float4 o;
            o.x = fmaxf(acc[i][0], 0.f);
            o.y = fmaxf(acc[i][1], 0.f);
            o.z = fmaxf(acc[i][2], 0.f);
            o.w = fmaxf(acc[i][3], 0.f);
            *(float4*)&Out[r * F + tx * 4] = o;
        }
    }
}

// ---------------- 64->16 GEMM ----------------
__global__ void k_gemm64x16(const float* __restrict__ H, const float* __restrict__ W1,
                            float* __restrict__ Out, int n) {
    __shared__ float Ws[64 * 16];
    __shared__ float Hs[16][65];
    int tid = threadIdx.x;  // 256
    for (int i = tid; i < 64 * 16; i += 256) Ws[i] = W1[i];
    int r0 = blockIdx.x * 16;
    for (int i = tid; i < 16 * 64; i += 256) {
        int rr = i >> 6, k = i & 63;
        int r = r0 + rr;
        Hs[rr][k] = (r < n) ? H[r * F + k] : 0.f;
    }
    __syncthreads();
    int rr = tid >> 4, j = tid & 15;
    float acc = 0.f;
#pragma unroll 8
    for (int k = 0; k < 64; k++) acc += Hs[rr][k] * Ws[k * 16 + j];
    int r = r0 + rr;
    if (r < n) Out[r * 16 + j] = acc;
}

// ---------------- 16->1 GEMV ----------------
__global__ void k_gemv16(const float* __restrict__ H16, const float* __restrict__ w2,
                         float* __restrict__ y, int n) {
    int r = blockIdx.x * blockDim.x + threadIdx.x;
    if (r >= n) return;
    float acc = 0.f;
#pragma unroll
    for (int j = 0; j < 16; j++) acc += H16[r * 16 + j] * w2[j];
    y[r] = acc;
}

// ---------------- launch ----------------
extern "C" void kernel_launch(void* const* d_in, const int* in_sizes, int n_in,
                              void* d_out, int out_size) {
    const float* x   = (const float*)d_in[0];
    const void*  ei  = d_in[1];
    const float* gw  = (const float*)d_in[2];  // (4,64,64)
    const float* w1  = (const float*)d_in[3];  // (64,16)
    const float* b1  = (const float*)d_in[4];
    const float* w2  = (const float*)d_in[5];  // (16,1)
    const float* b2  = (const float*)d_in[6];
    float* out = (float*)d_out;

    const int N = in_sizes[0] / F;
    const int E = in_sizes[1] / 2;

    float* bufA;  cudaGetSymbolAddress((void**)&bufA, g_bufA);
    float* bufB;  cudaGetSymbolAddress((void**)&bufB, g_bufB);
    float* bufP;  cudaGetSymbolAddress((void**)&bufP, g_bufP);
    float* t16;   cudaGetSymbolAddress((void**)&t16,  g_t16);
    float* p16;   cudaGetSymbolAddress((void**)&p16,  g_p16);
    float* yv;    cudaGetSymbolAddress((void**)&yv,   g_y);

    const int T = 256;
    int nb_n = (N + T - 1) / T;
    int nb_e = (E + T - 1) / T;
    int nb_scan = (N + 1023) / 1024;

    // graph norm + CSR build
    k_detect<<<1, 32>>>((const int*)ei);
    k_zero_cnt<<<nb_n, T>>>(N);
    k_convert_count<<<nb_e, T>>>(ei, E);
    k_dis<<<nb_n, T>>>(N);
    k_scan1<<<nb_scan, 1024>>>(N);
    k_scan2<<<1, 32>>>(nb_scan);
    k_scan3<<<nb_n, T>>>(N, E);
    k_scatter<<<nb_e, T>>>(E);

    // GCN2Conv stack
    int nb_p64 = (N + 3) / 4;
    int nb_g   = (N + 63) / 64;
    const float* hin = x;
    float* hout = bufA;
    for (int l = 0; l < NLAYER; l++) {
        k_prop64<<<nb_p64, 256>>>(hin, bufP, N);
        k_gemm_mix_relu<<<nb_g, 256>>>(bufP, x, gw + l * 64 * 64, hout, N);
        hin = hout;
        hout = (hout == bufA) ? bufB : bufA;
    }

    // GCNConv(64,16): lin -> propagate -> +b1
    int nb_g16 = (N + 15) / 16;
    k_gemm64x16<<<nb_g16, 256>>>(hin, w1, t16, N);
    k_prop16<<<nb_g16, 256>>>(t16, p16, b1, N);

    // GCNConv(16,1): lin -> propagate -> +b2 -> sigmoid
    k_gemv16<<<nb_n, T>>>(p16, w2, yv, N);
    k_prop1_sig<<<nb_n, T>>>(yv, b2, out, N);
}

// round 3
// speedup vs baseline: 2.1232x; 2.1232x over previous
#include <cuda_runtime.h>
#include <cuda_fp16.h>
#include <math.h>

#define MAXN 100000
#define MAXE 1000000
#define F 64
#define NLAYER 4
#define ALPHA 0.1f

// ---------------- device scratch (no cudaMalloc allowed) ----------------
__device__ int   g_is64;
__device__ int   g_cnt[MAXN];
__device__ int   g_ptr[MAXN + 1];
__device__ int   g_cur[MAXN];
__device__ int   g_rowv[MAXE];
__device__ int   g_colv[MAXE];
__device__ int   g_srcv[MAXE];
__device__ int   g_bsum[128];
__device__ float g_dis[MAXN];
__device__ float g_bufA[MAXN * F];
__device__ float g_bufB[MAXN * F];
__device__ float g_bufP[MAXN * F];
__device__ float g_t16[MAXN * 16];
__device__ float g_y[MAXN];

// ---------------- init: detect dtype + zero counters ----------------
__global__ void k_init(const int* ei32, int n) {
    int i = blockIdx.x * blockDim.x + threadIdx.x;
    if (i < n) g_cnt[i] = 0;
    if (i == 0) {
        // int64 nonneg indices < 2^31 -> all high words zero
        int odd_or = 0;
        for (int k = 1; k < 256; k += 2) odd_or |= ei32[k];
        g_is64 = (odd_or == 0) ? 1 : 0;
    }
}

// convert edges to int32 + in-degree histogram on col
__global__ void k_convert_count(const void* ei, int E) {
    int e = blockIdx.x * blockDim.x + threadIdx.x;
    if (e >= E) return;
    int r, c;
    if (g_is64) {
        const long long* p = (const long long*)ei;
        r = (int)p[e];
        c = (int)p[e + E];
    } else {
        const int* p = (const int*)ei;
        r = p[e];
        c = p[e + E];
    }
    g_rowv[e] = r;
    g_colv[e] = c;
    atomicAdd(&g_cnt[c], 1);
}

// ---------------- scan pass 1: per-block inclusive scan + dis ----------------
__global__ void k_scan1(int n) {
    __shared__ int s[1024];
    int i = blockIdx.x * 1024 + threadIdx.x;
    int v = (i < n) ? g_cnt[i] : 0;
    if (i < n) g_dis[i] = rsqrtf((float)v + 1.0f);  // +1 self loop
    s[threadIdx.x] = v;
    __syncthreads();
    for (int off = 1; off < 1024; off <<= 1) {
        int t = (threadIdx.x >= off) ? s[threadIdx.x - off] : 0;
        __syncthreads();
        s[threadIdx.x] += t;
        __syncthreads();
    }
    if (i < n) g_ptr[i] = s[threadIdx.x] - v;  // exclusive within block
    if (threadIdx.x == 1023) g_bsum[blockIdx.x] = s[1023];
}

// ---------------- scan pass 2 (block-offset fixup fused in) ----------------
__global__ void k_scan23(int n, int E) {
    __shared__ int sb[128];
    __shared__ int base;
    int tid = threadIdx.x;
    if (tid < 128) sb[tid] = (tid < (int)gridDim.x) ? g_bsum[tid] : 0;
    __syncthreads();
    if (tid == 0) {
        int r = 0;
        for (int b = 0; b < (int)blockIdx.x; b++) r += sb[b];
        base = r;
    }
    __syncthreads();
    int i = blockIdx.x * 1024 + tid;
    if (i < n) {
        int p = g_ptr[i] + base;
        g_ptr[i] = p;
        g_cur[i] = p;
    }
    if (i == 0) g_ptr[n] = E;
}

// ---------------- scatter edges into CSR + prescale x by dis ----------------
__global__ void k_scatter_scale(const float* __restrict__ x, int E, int n) {
    int i = blockIdx.x * blockDim.x + threadIdx.x;
    if (i < E) {
        int c = g_colv[i];
        int pos = atomicAdd(&g_cur[c], 1);
        g_srcv[pos] = g_rowv[i];
    } else {
        int j = i - E;  // float4 index into xs
        if (j < n * 16) {
            int node = j >> 4, q = j & 15;
            float4 v = ((const float4*)x)[node * 16 + q];
            float d = g_dis[node];
            v.x *= d; v.y *= d; v.z *= d; v.w *= d;
            ((float4*)g_bufA)[node * 16 + q] = v;  // xs lives in bufA
        }
    }
}

// ---------------- propagate 64-wide (warp per node, float2, mix fused) ----
// P[c] = (1-a)*d_c*(sum_src hs[src] + hs[c]) + a*x0[c],   hs = dis .* h
__global__ void k_prop64(const float* __restrict__ hs, const float* __restrict__ x0,
                         float* __restrict__ P, int n) {
    int node = blockIdx.x * 8 + (threadIdx.x >> 5);
    int lane = threadIdx.x & 31;
    if (node >= n) return;
    int beg = g_ptr[node], end = g_ptr[node + 1];
    const float2* H = (const float2*)hs;
    float sx = 0.f, sy = 0.f;
    int e = beg;
    for (; e + 4 <= end; e += 4) {
        int s0 = g_srcv[e], s1 = g_srcv[e + 1], s2 = g_srcv[e + 2], s3 = g_srcv[e + 3];
        float2 v0 = H[s0 * 32 + lane];
        float2 v1 = H[s1 * 32 + lane];
        float2 v2 = H[s2 * 32 + lane];
        float2 v3 = H[s3 * 32 + lane];
        sx += v0.x + v1.x + v2.x + v3.x;
        sy += v0.y + v1.y + v2.y + v3.y;
    }
    for (; e < end; e++) {
        int s0 = g_srcv[e];
        float2 v = H[s0 * 32 + lane];
        sx += v.x; sy += v.y;
    }
    float d = g_dis[node];
    float2 hself = H[node * 32 + lane];
    float2 xv = ((const float2*)x0)[node * 32 + lane];
    float2 o;
    o.x = (1.0f - ALPHA) * d * (sx + hself.x) + ALPHA * xv.x;
    o.y = (1.0f - ALPHA) * d * (sy + hself.y) + ALPHA * xv.y;
    ((float2*)P)[node * 32 + lane] = o;
}

// ---------------- GEMM 64x64 + relu (+optional dis row-scale) ----------------
#define SA 68
__global__ void k_gemm_relu(const float* __restrict__ P, const float* __restrict__ W,
                            float* __restrict__ Out, int n, int doscale) {
    __shared__ float Ws[64 * SA];
    __shared__ float As[64 * SA];
    int tid = threadIdx.x;  // 256 threads
    const float4* P4 = (const float4*)P;
    const float4* W4 = (const float4*)W;
    int r0 = blockIdx.x * 64;
    for (int i = tid; i < 1024; i += 256) {
        int k = i >> 4, q = i & 15;
        *(float4*)&Ws[k * SA + q * 4] = W4[i];
    }
    for (int i = tid; i < 1024; i += 256) {
        int rr = i >> 4, q = i & 15;
        int r = r0 + rr;
        float4 v = make_float4(0.f, 0.f, 0.f, 0.f);
        if (r < n) v = P4[r * 16 + q];
        *(float4*)&As[rr * SA + q * 4] = v;
    }
    __syncthreads();
    int tx = tid & 15, ty = tid >> 4;
    float acc[4][4] = {};
#pragma unroll 8
    for (int k = 0; k < 64; k++) {
        float4 w4 = *(const float4*)&Ws[k * SA + tx * 4];
        float a0 = As[(ty * 4 + 0) * SA + k];
        float a1 = As[(ty * 4 + 1) * SA + k];
        float a2 = As[(ty * 4 + 2) * SA + k];
        float a3 = As[(ty * 4 + 3) * SA + k];
        acc[0][0] += a0 * w4.x; acc[0][1] += a0 * w4.y; acc[0][2] += a0 * w4.z; acc[0][3] += a0 * w4.w;
        acc[1][0] += a1 * w4.x; acc[1][1] += a1 * w4.y; acc[1][2] += a1 * w4.z; acc[1][3] += a1 * w4.w;
        acc[2][0] += a2 * w4.x; acc[2][1] += a2 * w4.y; acc[2][2] += a2 * w4.z; acc[2][3] += a2 * w4.w;
        acc[3][0] += a3 * w4.x; acc[3][1] += a3 * w4.y; acc[3][2] += a3 * w4.z; acc[3][3] += a3 * w4.w;
    }
#pragma unroll
    for (int i = 0; i < 4; i++) {
        int r = r0 + ty * 4 + i;
        if (r < n) {
            float sc = doscale ? g_dis[r] : 1.0f;
            float4 o;
            o.x = fmaxf(acc[i][0], 0.f) * sc;
            o.y = fmaxf(acc[i][1], 0.f) * sc;
            o.z = fmaxf(acc[i][2], 0.f) * sc;
            o.w = fmaxf(acc[i][3], 0.f) * sc;
            *(float4*)&Out[r * F + tx * 4] = o;
        }
    }
}

// ---------------- 64->16 GEMM, output prescaled by dis ----------------
__global__ void k_gemm64x16(const float* __restrict__ H, const float* __restrict__ W1,
                            float* __restrict__ Out, int n) {
    __shared__ float Ws[64 * 16];
    __shared__ float Hs[16][65];
    int tid = threadIdx.x;  // 256
    for (int i = tid; i < 64 * 16; i += 256) Ws[i] = W1[i];
    int r0 = blockIdx.x * 16;
    for (int i = tid; i < 16 * 64; i += 256) {
        int rr = i >> 6, k = i & 63;
        int r = r0 + rr;
        Hs[rr][k] = (r < n) ? H[r * F + k] : 0.f;
    }
    __syncthreads();
    int rr = tid >> 4, j = tid & 15;
    float acc = 0.f;
#pragma unroll 8
    for (int k = 0; k < 64; k++) acc += Hs[rr][k] * Ws[k * 16 + j];
    int r = r0 + rr;
    if (r < n) Out[r * 16 + j] = acc * g_dis[r];  // prescale for next propagate
}

// ---------------- propagate 16-wide + b1, fused 16->1 GEMV, prescale ----------
// ys[node] = dis[node] * sum_f ( (d*(sum ts + ts_self) + b1[f]) * w2[f] )
__global__ void k_prop16_gemv(const float* __restrict__ ts, const float* __restrict__ b1,
                              const float* __restrict__ w2, float* __restrict__ ys, int n) {
    int t = threadIdx.x;
    int node = blockIdx.x * 16 + (t >> 4);
    int f = t & 15;
    bool ok = node < n;
    int beg = 0, end = 0;
    if (ok) { beg = g_ptr[node]; end = g_ptr[node + 1]; }
    float s = 0.f;
    int e = beg;
    for (; e + 4 <= end; e += 4) {
        int s0 = g_srcv[e], s1 = g_srcv[e + 1], s2 = g_srcv[e + 2], s3 = g_srcv[e + 3];
        s += ts[s0 * 16 + f] + ts[s1 * 16 + f] + ts[s2 * 16 + f] + ts[s3 * 16 + f];
    }
    for (; e < end; e++) s += ts[g_srcv[e] * 16 + f];
    float d = ok ? g_dis[node] : 0.f;
    float self = ok ? ts[node * 16 + f] : 0.f;
    float val = d * (s + self) + b1[f];
    float prod = val * w2[f];
    prod += __shfl_xor_sync(0xffffffffu, prod, 8);
    prod += __shfl_xor_sync(0xffffffffu, prod, 4);
    prod += __shfl_xor_sync(0xffffffffu, prod, 2);
    prod += __shfl_xor_sync(0xffffffffu, prod, 1);
    if (ok && f == 0) ys[node] = d * prod;
}

// ---------------- scalar propagate + b2 + sigmoid ----------------
__global__ void k_prop1_sig(const float* __restrict__ ys, const float* __restrict__ b2,
                            float* __restrict__ out, int n) {
    int node = blockIdx.x * blockDim.x + threadIdx.x;
    if (node >= n) return;
    int beg = g_ptr[node], end = g_ptr[node + 1];
    float s = 0.f;
    int e = beg;
    for (; e + 4 <= end; e += 4) {
        int s0 = g_srcv[e], s1 = g_srcv[e + 1], s2 = g_srcv[e + 2], s3 = g_srcv[e + 3];
        s += ys[s0] + ys[s1] + ys[s2] + ys[s3];
    }
    for (; e < end; e++) s += ys[g_srcv[e]];
    float d = g_dis[node];
    float v = d * (s + ys[node]) + b2[0];
    out[node] = 1.0f / (1.0f + expf(-v));
}

// ---------------- launch ----------------
extern "C" void kernel_launch(void* const* d_in, const int* in_sizes, int n_in,
                              void* d_out, int out_size) {
    const float* x  = (const float*)d_in[0];
    const void*  ei = d_in[1];
    const float* gw = (const float*)d_in[2];  // (4,64,64)
    const float* w1 = (const float*)d_in[3];  // (64,16)
    const float* b1 = (const float*)d_in[4];
    const float* w2 = (const float*)d_in[5];  // (16,1)
    const float* b2 = (const float*)d_in[6];
    float* out = (float*)d_out;

    const int N = in_sizes[0] / F;
    const int E = in_sizes[1] / 2;

    float* bufA; cudaGetSymbolAddress((void**)&bufA, g_bufA);
    float* bufB; cudaGetSymbolAddress((void**)&bufB, g_bufB);
    float* bufP; cudaGetSymbolAddress((void**)&bufP, g_bufP);
    float* t16;  cudaGetSymbolAddress((void**)&t16,  g_t16);
    float* yv;   cudaGetSymbolAddress((void**)&yv,   g_y);

    const int T = 256;
    int nb_n = (N + T - 1) / T;
    int nb_e = (E + T - 1) / T;
    int nb_scan = (N + 1023) / 1024;
    int nb_ss = (E + N * 16 + T - 1) / T;

    // 0..4: graph norm + CSR build (+ x prescale)
    k_init<<<nb_n, T>>>((const int*)ei, N);
    k_convert_count<<<nb_e, T>>>(ei, E);
    k_scan1<<<nb_scan, 1024>>>(N);
    k_scan23<<<nb_scan, 1024>>>(N, E);
    k_scatter_scale<<<nb_ss, T>>>(x, E, N);

    // GCN2Conv stack (hs buffers alternate; xs starts in bufA)
    int nb_p64 = (N + 7) / 8;
    int nb_g   = (N + 63) / 64;
    const float* hin = bufA;
    float* hout = bufB;
    for (int l = 0; l < NLAYER; l++) {
        k_prop64<<<nb_p64, 256>>>(hin, x, bufP, N);
        k_gemm_relu<<<nb_g, 256>>>(bufP, gw + l * 64 * 64, hout, N, l < NLAYER - 1 ? 1 : 0);
        hin = hout;
        hout = (hout == bufA) ? bufB : bufA;
    }

    // GCNConv(64,16): lin(+prescale) -> propagate(+b1) fused with GEMV(+prescale)
    int nb_g16 = (N + 15) / 16;
    k_gemm64x16<<<nb_g16, 256>>>(hin, w1, t16, N);
    k_prop16_gemv<<<nb_g16, 256>>>(t16, b1, w2, yv, N);

    // GCNConv(16,1) propagate + b2 + sigmoid
    k_prop1_sig<<<nb_n, T>>>(yv, b2, out, N);
}